// round 2
// baseline (speedup 1.0000x reference)
#include <cuda_runtime.h>

// ---------------------------------------------------------------------------
// MultiHeadedAttention: B=2, S=2048, H=16, d_k=64, d_model=1024, fp32.
//   q = split_heads(query @ Wq^T + bq)   (same for k, v)
//   scores = q k^T / 8 ; mask==0 -> -1e9 ; softmax ; attn = p v
//   out = merge_heads(attn) @ Wo^T + bo
// Round 0: exact fp32 SIMT implementation (SGEMM + flash attention).
// ---------------------------------------------------------------------------

#define B_  2
#define S_  2048
#define H_  16
#define DK  64
#define DM  1024
#define M_  (B_ * S_)   // 4096

// Scratch (device globals: no allocations allowed in kernel_launch)
__device__ float g_Q[(size_t)B_ * H_ * S_ * DK];     // [b][h][s][d]
__device__ float g_K[(size_t)B_ * H_ * S_ * DK];
__device__ float g_V[(size_t)B_ * H_ * S_ * DK];
__device__ float g_attn[(size_t)M_ * DM];            // [b*s][h*64+d]

// ---------------------------------------------------------------------------
// SGEMM-NT core: Y[M,N] = X[M,K] * W[N,K]^T ; M=4096, N=1024, K=1024 fixed.
// 128x128 block tile, BK=16, 256 threads, 8x8 per-thread micro-tile.
// As/Bs stored k-major transposed with +4 pad -> 2-way conflicts max.
// ---------------------------------------------------------------------------
#define BM 128
#define BN 128
#define BK 16
#define TM 8
#define TN 8
#define PADM (BM + 4)

__device__ __forceinline__ void sgemm_nt_core(
    const float* __restrict__ X, const float* __restrict__ W,
    float acc[TM][TN], int m0, int n0)
{
    __shared__ float As[BK][PADM];
    __shared__ float Bs[BK][PADM];

    const int tid  = threadIdx.x;
    const int tx   = tid & 15;
    const int ty   = tid >> 4;
    const int trow = ty * TM;
    const int tcol = tx * TN;

    for (int k0 = 0; k0 < DM; k0 += BK) {
        // Load X tile [128 rows x 16 k] as float4, store transposed As[k][row]
        #pragma unroll
        for (int v = tid; v < (BM * BK) / 4; v += 256) {   // 512 float4
            int row = v >> 2;
            int c4  = (v & 3) * 4;
            float4 x = *(const float4*)(X + (size_t)(m0 + row) * DM + k0 + c4);
            As[c4 + 0][row] = x.x;
            As[c4 + 1][row] = x.y;
            As[c4 + 2][row] = x.z;
            As[c4 + 3][row] = x.w;
        }
        #pragma unroll
        for (int v = tid; v < (BN * BK) / 4; v += 256) {
            int row = v >> 2;
            int c4  = (v & 3) * 4;
            float4 w = *(const float4*)(W + (size_t)(n0 + row) * DM + k0 + c4);
            Bs[c4 + 0][row] = w.x;
            Bs[c4 + 1][row] = w.y;
            Bs[c4 + 2][row] = w.z;
            Bs[c4 + 3][row] = w.w;
        }
        __syncthreads();

        #pragma unroll
        for (int k = 0; k < BK; k++) {
            float a[TM], b[TN];
            *(float4*)&a[0] = *(const float4*)&As[k][trow];
            *(float4*)&a[4] = *(const float4*)&As[k][trow + 4];
            *(float4*)&b[0] = *(const float4*)&Bs[k][tcol];
            *(float4*)&b[4] = *(const float4*)&Bs[k][tcol + 4];
            #pragma unroll
            for (int i = 0; i < TM; i++)
                #pragma unroll
                for (int j = 0; j < TN; j++)
                    acc[i][j] += a[i] * b[j];
        }
        __syncthreads();
    }
}

// QKV projection: gridDim.z selects q/k/v. Epilogue writes head-split layout.
__global__ __launch_bounds__(256) void qkv_proj_kernel(
    const float* __restrict__ q_in, const float* __restrict__ k_in,
    const float* __restrict__ v_in,
    const float* __restrict__ Wq, const float* __restrict__ Wk,
    const float* __restrict__ Wv,
    const float* __restrict__ bq, const float* __restrict__ bk,
    const float* __restrict__ bv)
{
    const float *X, *W, *bias;
    float* out;
    if (blockIdx.z == 0)      { X = q_in; W = Wq; bias = bq; out = g_Q; }
    else if (blockIdx.z == 1) { X = k_in; W = Wk; bias = bk; out = g_K; }
    else                      { X = v_in; W = Wv; bias = bv; out = g_V; }

    float acc[TM][TN];
    #pragma unroll
    for (int i = 0; i < TM; i++)
        #pragma unroll
        for (int j = 0; j < TN; j++) acc[i][j] = 0.f;

    const int m0 = blockIdx.x * BM;
    const int n0 = blockIdx.y * BN;
    sgemm_nt_core(X, W, acc, m0, n0);

    const int tid = threadIdx.x;
    const int tx  = tid & 15;
    const int ty  = tid >> 4;
    #pragma unroll
    for (int i = 0; i < TM; i++) {
        int m  = m0 + ty * TM + i;
        int bb = m >> 11;            // / S_
        int s  = m & (S_ - 1);
        #pragma unroll
        for (int jj = 0; jj < TN; jj += 4) {
            int n = n0 + tx * TN + jj;
            int h = n >> 6;
            int d = n & 63;
            float4 val;
            val.x = acc[i][jj + 0] + bias[n + 0];
            val.y = acc[i][jj + 1] + bias[n + 1];
            val.z = acc[i][jj + 2] + bias[n + 2];
            val.w = acc[i][jj + 3] + bias[n + 3];
            *(float4*)&out[(((size_t)(bb * H_ + h) * S_) + s) * DK + d] = val;
        }
    }
}

// Output projection: Y = g_attn @ Wo^T + bo, plain [M, DM] store to d_out.
__global__ __launch_bounds__(256) void out_proj_kernel(
    const float* __restrict__ Wo, const float* __restrict__ bo,
    float* __restrict__ out)
{
    float acc[TM][TN];
    #pragma unroll
    for (int i = 0; i < TM; i++)
        #pragma unroll
        for (int j = 0; j < TN; j++) acc[i][j] = 0.f;

    const int m0 = blockIdx.x * BM;
    const int n0 = blockIdx.y * BN;
    sgemm_nt_core(g_attn, Wo, acc, m0, n0);

    const int tid = threadIdx.x;
    const int tx  = tid & 15;
    const int ty  = tid >> 4;
    #pragma unroll
    for (int i = 0; i < TM; i++) {
        int m = m0 + ty * TM + i;
        #pragma unroll
        for (int jj = 0; jj < TN; jj += 4) {
            int n = n0 + tx * TN + jj;
            float4 val;
            val.x = acc[i][jj + 0] + bo[n + 0];
            val.y = acc[i][jj + 1] + bo[n + 1];
            val.z = acc[i][jj + 2] + bo[n + 2];
            val.w = acc[i][jj + 3] + bo[n + 3];
            *(float4*)&out[(size_t)m * DM + n] = val;
        }
    }
}

// ---------------------------------------------------------------------------
// Flash attention: per block = one (b, h, 64-row q tile). 256 threads (16x16),
// 4x4 micro-tiles. Online softmax. All smem tiles padded to stride 65
// (bank = (row + col) mod 32 -> <=2-way conflicts). Mask staged via smem.
// ---------------------------------------------------------------------------
#define FBM 64
#define FBN 64
#define FPAD 65

__global__ __launch_bounds__(256) void flash_kernel(const int* __restrict__ mask)
{
    extern __shared__ float smem[];
    float* Qs = smem;                    // [64][65]  (pre-scaled by 1/8)
    float* Ks = Qs + 64 * FPAD;          // [64][65]  K rows (c-major: Ks[c][d])
    float* Vs = Ks + 64 * FPAD;          // [64][65]  Vs[kk][d]
    float* Ps = Vs + 64 * FPAD;          // [64][65]  Ps[r][kk]
    int*   Ms = (int*)(Ps + 64 * FPAD);  // [64][64]

    const int tid = threadIdx.x;
    const int tx  = tid & 15;
    const int ty  = tid >> 4;
    const int q0  = blockIdx.x * FBM;
    const int h   = blockIdx.y;
    const int b   = blockIdx.z;

    const float* Qg = g_Q + (size_t)(b * H_ + h) * S_ * DK;
    const float* Kg = g_K + (size_t)(b * H_ + h) * S_ * DK;
    const float* Vg = g_V + (size_t)(b * H_ + h) * S_ * DK;
    const int*   Mg = mask + (size_t)b * S_ * S_;

    // Load Q tile once, pre-scaled by 1/sqrt(d_k) = 0.125 (exact).
    const float qscale = 0.125f;
    for (int v = tid; v < 64 * 16; v += 256) {
        int r  = v >> 4;
        int c4 = (v & 15) * 4;
        float4 q = *(const float4*)(Qg + (size_t)(q0 + r) * DK + c4);
        float* dst = &Qs[r * FPAD + c4];
        dst[0] = q.x * qscale; dst[1] = q.y * qscale;
        dst[2] = q.z * qscale; dst[3] = q.w * qscale;
    }

    float m_i[4], l_i[4], o[4][4];
    #pragma unroll
    for (int i = 0; i < 4; i++) {
        m_i[i] = -1e30f;
        l_i[i] = 0.f;
        #pragma unroll
        for (int j = 0; j < 4; j++) o[i][j] = 0.f;
    }

    for (int n0t = 0; n0t < S_; n0t += FBN) {
        // Load K, V tiles (float4 global, scalar smem stores: 2-way max)
        for (int v = tid; v < 64 * 16; v += 256) {
            int r  = v >> 4;
            int c4 = (v & 15) * 4;
            float4 kk = *(const float4*)(Kg + (size_t)(n0t + r) * DK + c4);
            float* kd = &Ks[r * FPAD + c4];
            kd[0] = kk.x; kd[1] = kk.y; kd[2] = kk.z; kd[3] = kk.w;
            float4 vv = *(const float4*)(Vg + (size_t)(n0t + r) * DK + c4);
            float* vd = &Vs[r * FPAD + c4];
            vd[0] = vv.x; vd[1] = vv.y; vd[2] = vv.z; vd[3] = vv.w;
        }
        // Mask tile (int4 aligned, stride 64)
        for (int v = tid; v < 64 * 16; v += 256) {
            int r  = v >> 4;
            int c4 = (v & 15) * 4;
            int4 mm = *(const int4*)(Mg + (size_t)(q0 + r) * S_ + n0t + c4);
            *(int4*)&Ms[r * 64 + c4] = mm;
        }
        __syncthreads();

        // S = (Q/8) K^T  -- 4x4 micro-tile, reduction over d
        float s[4][4];
        #pragma unroll
        for (int i = 0; i < 4; i++)
            #pragma unroll
            for (int j = 0; j < 4; j++) s[i][j] = 0.f;

        #pragma unroll 16
        for (int d = 0; d < 64; d++) {
            float a0 = Qs[(ty * 4 + 0) * FPAD + d];
            float a1 = Qs[(ty * 4 + 1) * FPAD + d];
            float a2 = Qs[(ty * 4 + 2) * FPAD + d];
            float a3 = Qs[(ty * 4 + 3) * FPAD + d];
            float b0 = Ks[(tx * 4 + 0) * FPAD + d];
            float b1 = Ks[(tx * 4 + 1) * FPAD + d];
            float b2 = Ks[(tx * 4 + 2) * FPAD + d];
            float b3 = Ks[(tx * 4 + 3) * FPAD + d];
            s[0][0] += a0 * b0; s[0][1] += a0 * b1; s[0][2] += a0 * b2; s[0][3] += a0 * b3;
            s[1][0] += a1 * b0; s[1][1] += a1 * b1; s[1][2] += a1 * b2; s[1][3] += a1 * b3;
            s[2][0] += a2 * b0; s[2][1] += a2 * b1; s[2][2] += a2 * b2; s[2][3] += a2 * b3;
            s[3][0] += a3 * b0; s[3][1] += a3 * b1; s[3][2] += a3 * b2; s[3][3] += a3 * b3;
        }

        // Mask + online softmax update (row groups: 16 lanes with same ty)
        #pragma unroll
        for (int i = 0; i < 4; i++) {
            const int r = ty * 4 + i;
            #pragma unroll
            for (int j = 0; j < 4; j++)
                if (Ms[r * 64 + tx * 4 + j] == 0) s[i][j] = -1e9f;

            float mloc = fmaxf(fmaxf(s[i][0], s[i][1]), fmaxf(s[i][2], s[i][3]));
            #pragma unroll
            for (int off = 8; off >= 1; off >>= 1)
                mloc = fmaxf(mloc, __shfl_xor_sync(0xffffffffu, mloc, off, 16));

            float mn = fmaxf(m_i[i], mloc);
            float f  = __expf(m_i[i] - mn);
            m_i[i] = mn;

            float rs = 0.f;
            #pragma unroll
            for (int j = 0; j < 4; j++) {
                s[i][j] = __expf(s[i][j] - mn);
                rs += s[i][j];
            }
            #pragma unroll
            for (int off = 8; off >= 1; off >>= 1)
                rs += __shfl_xor_sync(0xffffffffu, rs, off, 16);

            l_i[i] = l_i[i] * f + rs;
            #pragma unroll
            for (int j = 0; j < 4; j++) o[i][j] *= f;

            // stage P for the PV GEMM
            #pragma unroll
            for (int j = 0; j < 4; j++)
                Ps[r * FPAD + tx * 4 + j] = s[i][j];
        }
        __syncthreads();

        // O += P V  -- reduction over kk (tile column)
        #pragma unroll 16
        for (int k = 0; k < 64; k++) {
            float p0 = Ps[(ty * 4 + 0) * FPAD + k];
            float p1 = Ps[(ty * 4 + 1) * FPAD + k];
            float p2 = Ps[(ty * 4 + 2) * FPAD + k];
            float p3 = Ps[(ty * 4 + 3) * FPAD + k];
            float v0 = Vs[k * FPAD + tx * 4 + 0];
            float v1 = Vs[k * FPAD + tx * 4 + 1];
            float v2 = Vs[k * FPAD + tx * 4 + 2];
            float v3 = Vs[k * FPAD + tx * 4 + 3];
            o[0][0] += p0 * v0; o[0][1] += p0 * v1; o[0][2] += p0 * v2; o[0][3] += p0 * v3;
            o[1][0] += p1 * v0; o[1][1] += p1 * v1; o[1][2] += p1 * v2; o[1][3] += p1 * v3;
            o[2][0] += p2 * v0; o[2][1] += p2 * v1; o[2][2] += p2 * v2; o[2][3] += p2 * v3;
            o[3][0] += p3 * v0; o[3][1] += p3 * v1; o[3][2] += p3 * v2; o[3][3] += p3 * v3;
        }
        __syncthreads();   // protect Ks/Vs/Ps before next tile load
    }

    // Epilogue: normalize and store to merged-head layout [b*s][h*64+d]
    #pragma unroll
    for (int i = 0; i < 4; i++) {
        float inv = 1.0f / l_i[i];
        int s_row = q0 + ty * 4 + i;
        float4 val;
        val.x = o[i][0] * inv;
        val.y = o[i][1] * inv;
        val.z = o[i][2] * inv;
        val.w = o[i][3] * inv;
        *(float4*)&g_attn[(size_t)(b * S_ + s_row) * DM + h * DK + tx * 4] = val;
    }
}

// ---------------------------------------------------------------------------
extern "C" void kernel_launch(void* const* d_in, const int* in_sizes, int n_in,
                              void* d_out, int out_size)
{
    (void)in_sizes; (void)n_in; (void)out_size;
    const float* query = (const float*)d_in[0];
    const float* key   = (const float*)d_in[1];
    const float* value = (const float*)d_in[2];
    const int*   mask  = (const int*)d_in[3];
    const float* Wq    = (const float*)d_in[4];
    const float* bq    = (const float*)d_in[5];
    const float* Wk    = (const float*)d_in[6];
    const float* bk    = (const float*)d_in[7];
    const float* Wv    = (const float*)d_in[8];
    const float* bv    = (const float*)d_in[9];
    const float* Wo    = (const float*)d_in[10];
    const float* bo    = (const float*)d_in[11];
    float* out = (float*)d_out;

    // 1) QKV projections (fused into one launch via gridDim.z)
    dim3 gproj(M_ / BM, DM / BN, 3);   // (32, 8, 3)
    qkv_proj_kernel<<<gproj, 256>>>(query, key, value, Wq, Wk, Wv, bq, bk, bv);

    // 2) Flash attention
    const int smem_bytes = 4 * 64 * FPAD * (int)sizeof(float)
                         + 64 * 64 * (int)sizeof(int);   // 82,944 B
    cudaFuncSetAttribute(flash_kernel,
                         cudaFuncAttributeMaxDynamicSharedMemorySize, smem_bytes);
    dim3 gflash(S_ / FBM, H_, B_);     // (32, 16, 2)
    flash_kernel<<<gflash, 256, smem_bytes>>>(mask);

    // 3) Output projection
    dim3 gout(M_ / BM, DM / BN);       // (32, 8)
    out_proj_kernel<<<gout, 256>>>(Wo, bo, out);
}

// round 4
// speedup vs baseline: 1.1569x; 1.1569x over previous
#include <cuda_runtime.h>

// ---------------------------------------------------------------------------
// MultiHeadedAttention: B=2, S=2048, H=16, d_k=64, d_model=1024, fp32.
// R2: flash rework (128x64 tile, 8x4 micro, vectorized LDS via transposed
// smem layouts) + register double-buffered SGEMM.
// ---------------------------------------------------------------------------

#define B_  2
#define S_  2048
#define H_  16
#define DK  64
#define DM  1024
#define M_  (B_ * S_)   // 4096

// Scratch (device globals: no allocations allowed in kernel_launch)
__device__ float g_Q[(size_t)B_ * H_ * S_ * DK];     // [b][h][s][d]
__device__ float g_K[(size_t)B_ * H_ * S_ * DK];
__device__ float g_V[(size_t)B_ * H_ * S_ * DK];
__device__ float g_attn[(size_t)M_ * DM];            // [b*s][h*64+d]

// ---------------------------------------------------------------------------
// SGEMM-NT core: Y[M,N] = X[M,K] * W[N,K]^T ; K = DM = 1024.
// 128x128 tile, BK=16, 256 threads, 8x8 micro-tile, register double buffer.
// ---------------------------------------------------------------------------
#define BM 128
#define BN 128
#define BK 16
#define TM 8
#define TN 8
#define PADM (BM + 4)

__device__ __forceinline__ void sgemm_nt_core(
    const float* __restrict__ X, const float* __restrict__ W,
    float acc[TM][TN], int m0, int n0)
{
    __shared__ float As[BK][PADM];
    __shared__ float Bs[BK][PADM];

    const int tid  = threadIdx.x;
    const int tx   = tid & 15;
    const int ty   = tid >> 4;
    const int trow = ty * TM;
    const int tcol = tx * TN;

    // Each thread owns 2 float4 slots per tile per operand.
    const int r0 = tid >> 2;            // 0..63
    const int c0 = (tid & 3) * 4;       // 0,4,8,12

    const float* Xp = X + (size_t)(m0 + r0) * DM + c0;
    const float* Wp = W + (size_t)(n0 + r0) * DM + c0;

    float4 xa0 = *(const float4*)(Xp);
    float4 xa1 = *(const float4*)(Xp + (size_t)64 * DM);
    float4 wb0 = *(const float4*)(Wp);
    float4 wb1 = *(const float4*)(Wp + (size_t)64 * DM);

    for (int k0 = 0; k0 < DM; k0 += BK) {
        // Commit staged registers to smem (transposed: As[k][row])
        As[c0 + 0][r0] = xa0.x; As[c0 + 1][r0] = xa0.y;
        As[c0 + 2][r0] = xa0.z; As[c0 + 3][r0] = xa0.w;
        As[c0 + 0][r0 + 64] = xa1.x; As[c0 + 1][r0 + 64] = xa1.y;
        As[c0 + 2][r0 + 64] = xa1.z; As[c0 + 3][r0 + 64] = xa1.w;
        Bs[c0 + 0][r0] = wb0.x; Bs[c0 + 1][r0] = wb0.y;
        Bs[c0 + 2][r0] = wb0.z; Bs[c0 + 3][r0] = wb0.w;
        Bs[c0 + 0][r0 + 64] = wb1.x; Bs[c0 + 1][r0 + 64] = wb1.y;
        Bs[c0 + 2][r0 + 64] = wb1.z; Bs[c0 + 3][r0 + 64] = wb1.w;
        __syncthreads();

        // Prefetch next tile while computing this one
        if (k0 + BK < DM) {
            xa0 = *(const float4*)(Xp + k0 + BK);
            xa1 = *(const float4*)(Xp + (size_t)64 * DM + k0 + BK);
            wb0 = *(const float4*)(Wp + k0 + BK);
            wb1 = *(const float4*)(Wp + (size_t)64 * DM + k0 + BK);
        }

        #pragma unroll
        for (int k = 0; k < BK; k++) {
            float a[TM], b[TN];
            *(float4*)&a[0] = *(const float4*)&As[k][trow];
            *(float4*)&a[4] = *(const float4*)&As[k][trow + 4];
            *(float4*)&b[0] = *(const float4*)&Bs[k][tcol];
            *(float4*)&b[4] = *(const float4*)&Bs[k][tcol + 4];
            #pragma unroll
            for (int i = 0; i < TM; i++)
                #pragma unroll
                for (int j = 0; j < TN; j++)
                    acc[i][j] += a[i] * b[j];
        }
        __syncthreads();
    }
}

// QKV projection: gridDim.z selects q/k/v. Epilogue writes head-split layout.
__global__ __launch_bounds__(256, 2) void qkv_proj_kernel(
    const float* __restrict__ q_in, const float* __restrict__ k_in,
    const float* __restrict__ v_in,
    const float* __restrict__ Wq, const float* __restrict__ Wk,
    const float* __restrict__ Wv,
    const float* __restrict__ bq, const float* __restrict__ bk,
    const float* __restrict__ bv)
{
    const float *X, *W, *bias;
    float* out;
    if (blockIdx.z == 0)      { X = q_in; W = Wq; bias = bq; out = g_Q; }
    else if (blockIdx.z == 1) { X = k_in; W = Wk; bias = bk; out = g_K; }
    else                      { X = v_in; W = Wv; bias = bv; out = g_V; }

    float acc[TM][TN];
    #pragma unroll
    for (int i = 0; i < TM; i++)
        #pragma unroll
        for (int j = 0; j < TN; j++) acc[i][j] = 0.f;

    const int m0 = blockIdx.x * BM;
    const int n0 = blockIdx.y * BN;
    sgemm_nt_core(X, W, acc, m0, n0);

    const int tid = threadIdx.x;
    const int tx  = tid & 15;
    const int ty  = tid >> 4;
    #pragma unroll
    for (int i = 0; i < TM; i++) {
        int m  = m0 + ty * TM + i;
        int bb = m >> 11;            // / S_
        int s  = m & (S_ - 1);
        #pragma unroll
        for (int jj = 0; jj < TN; jj += 4) {
            int n = n0 + tx * TN + jj;
            int h = n >> 6;
            int d = n & 63;
            float4 val;
            val.x = acc[i][jj + 0] + bias[n + 0];
            val.y = acc[i][jj + 1] + bias[n + 1];
            val.z = acc[i][jj + 2] + bias[n + 2];
            val.w = acc[i][jj + 3] + bias[n + 3];
            *(float4*)&out[(((size_t)(bb * H_ + h) * S_) + s) * DK + d] = val;
        }
    }
}

// Output projection: Y = g_attn @ Wo^T + bo, plain [M, DM] store to d_out.
__global__ __launch_bounds__(256, 2) void out_proj_kernel(
    const float* __restrict__ Wo, const float* __restrict__ bo,
    float* __restrict__ out)
{
    float acc[TM][TN];
    #pragma unroll
    for (int i = 0; i < TM; i++)
        #pragma unroll
        for (int j = 0; j < TN; j++) acc[i][j] = 0.f;

    const int m0 = blockIdx.x * BM;
    const int n0 = blockIdx.y * BN;
    sgemm_nt_core(g_attn, Wo, acc, m0, n0);

    const int tid = threadIdx.x;
    const int tx  = tid & 15;
    const int ty  = tid >> 4;
    #pragma unroll
    for (int i = 0; i < TM; i++) {
        int m = m0 + ty * TM + i;
        #pragma unroll
        for (int jj = 0; jj < TN; jj += 4) {
            int n = n0 + tx * TN + jj;
            float4 val;
            val.x = acc[i][jj + 0] + bo[n + 0];
            val.y = acc[i][jj + 1] + bo[n + 1];
            val.z = acc[i][jj + 2] + bo[n + 2];
            val.w = acc[i][jj + 3] + bo[n + 3];
            *(float4*)&out[(size_t)m * DM + n] = val;
        }
    }
}

// ---------------------------------------------------------------------------
// Flash attention: per block = one (b, h, 128-row q tile), 64-col kv tiles.
// 256 threads (16x16), 8x4 micro-tiles. Transposed smem layouts so inner
// loops are 3x LDS.128 : 32 FMA. Mask read directly from global (coalesced).
//   Qt[d][r]  pad 132   (d-major, r-contiguous -> vector a-fragment)
//   Kt[d][c]  pad 68    (d-major, c-contiguous -> vector b-fragment)
//   Vs[k][d]  pad 68    (natural, d-contiguous -> vector b-fragment)
//   Pt[k][r]  pad 140   (k-major, r-contiguous -> vector a-fragment)
// ---------------------------------------------------------------------------
#define FBM 128
#define FBN 64
#define QPAD 132
#define KPAD 68
#define VPAD 68
#define PPAD 140
#define SM_QT (64 * QPAD)          // 8448 floats
#define SM_KT (64 * KPAD)          // 4352
#define SM_VS (64 * VPAD)          // 4352
#define SM_PT (64 * PPAD)          // 8960
#define FLASH_SMEM ((SM_QT + SM_KT + SM_VS + SM_PT) * (int)sizeof(float))

__global__ __launch_bounds__(256, 2) void flash_kernel(const int* __restrict__ mask)
{
    extern __shared__ float smem[];
    float* Qt = smem;
    float* Kt = Qt + SM_QT;
    float* Vs = Kt + SM_KT;
    float* Pt = Vs + SM_VS;

    const int tid = threadIdx.x;
    const int tx  = tid & 15;          // 0..15 -> kv col group (QK) / d group (PV)
    const int ty  = tid >> 4;          // 0..15 -> q row group (8 rows)
    const int q0  = blockIdx.x * FBM;
    const int h   = blockIdx.y;
    const int b   = blockIdx.z;

    const float* Qg = g_Q + (size_t)(b * H_ + h) * S_ * DK;
    const float* Kg = g_K + (size_t)(b * H_ + h) * S_ * DK;
    const float* Vg = g_V + (size_t)(b * H_ + h) * S_ * DK;
    const int*   Mg = mask + (size_t)b * S_ * S_;

    // Load Q tile once, transposed + pre-scaled by 1/8.
    // Mapping: warp = 32 consecutive r, same d4 -> conflict-free STS.
    const float qscale = 0.125f;
    #pragma unroll
    for (int v = tid; v < 128 * 16; v += 256) {
        int r  = v & 127;
        int d4 = (v >> 7) * 4;
        float4 q = *(const float4*)(Qg + (size_t)(q0 + r) * DK + d4);
        Qt[(d4 + 0) * QPAD + r] = q.x * qscale;
        Qt[(d4 + 1) * QPAD + r] = q.y * qscale;
        Qt[(d4 + 2) * QPAD + r] = q.z * qscale;
        Qt[(d4 + 3) * QPAD + r] = q.w * qscale;
    }

    float m_i[8], l_i[8], o[8][4];
    #pragma unroll
    for (int i = 0; i < 8; i++) {
        m_i[i] = -1e30f;
        l_i[i] = 0.f;
        #pragma unroll
        for (int j = 0; j < 4; j++) o[i][j] = 0.f;
    }

    for (int n0t = 0; n0t < S_; n0t += FBN) {
        // K tile: transposed store (warp = consecutive c -> conflict-free STS)
        #pragma unroll
        for (int v = tid; v < 64 * 16; v += 256) {
            int c  = v & 63;
            int d4 = (v >> 6) * 4;
            float4 kk = *(const float4*)(Kg + (size_t)(n0t + c) * DK + d4);
            Kt[(d4 + 0) * KPAD + c] = kk.x;
            Kt[(d4 + 1) * KPAD + c] = kk.y;
            Kt[(d4 + 2) * KPAD + c] = kk.z;
            Kt[(d4 + 3) * KPAD + c] = kk.w;
        }
        // V tile: natural layout, coalesced load
        #pragma unroll
        for (int v = tid; v < 64 * 16; v += 256) {
            int k  = v >> 4;
            int c4 = (v & 15) * 4;
            float4 vv = *(const float4*)(Vg + (size_t)(n0t + k) * DK + c4);
            float* vd = &Vs[k * VPAD + c4];
            vd[0] = vv.x; vd[1] = vv.y; vd[2] = vv.z; vd[3] = vv.w;
        }
        __syncthreads();

        // S = (Q/8) K^T : 8x4 micro-tile, 3x LDS.128 + 32 FMA per d
        float s[8][4];
        #pragma unroll
        for (int i = 0; i < 8; i++)
            #pragma unroll
            for (int j = 0; j < 4; j++) s[i][j] = 0.f;

        #pragma unroll 8
        for (int d = 0; d < 64; d++) {
            float a[8], bb[4];
            *(float4*)&a[0] = *(const float4*)&Qt[d * QPAD + ty * 8];
            *(float4*)&a[4] = *(const float4*)&Qt[d * QPAD + ty * 8 + 4];
            *(float4*)&bb[0] = *(const float4*)&Kt[d * KPAD + tx * 4];
            #pragma unroll
            for (int i = 0; i < 8; i++)
                #pragma unroll
                for (int j = 0; j < 4; j++)
                    s[i][j] += a[i] * bb[j];
        }

        // Mask + online softmax (rows r = ty*8+i, 16 tx lanes per row)
        #pragma unroll
        for (int i = 0; i < 8; i++) {
            const int r = ty * 8 + i;
            int4 mm = *(const int4*)(Mg + (size_t)(q0 + r) * S_ + n0t + tx * 4);
            if (mm.x == 0) s[i][0] = -1e9f;
            if (mm.y == 0) s[i][1] = -1e9f;
            if (mm.z == 0) s[i][2] = -1e9f;
            if (mm.w == 0) s[i][3] = -1e9f;

            float mloc = fmaxf(fmaxf(s[i][0], s[i][1]), fmaxf(s[i][2], s[i][3]));
            #pragma unroll
            for (int off = 8; off >= 1; off >>= 1)
                mloc = fmaxf(mloc, __shfl_xor_sync(0xffffffffu, mloc, off, 16));

            float mn = fmaxf(m_i[i], mloc);
            float f  = __expf(m_i[i] - mn);
            m_i[i] = mn;

            float rs = 0.f;
            #pragma unroll
            for (int j = 0; j < 4; j++) {
                s[i][j] = __expf(s[i][j] - mn);
                rs += s[i][j];
            }
            #pragma unroll
            for (int off = 8; off >= 1; off >>= 1)
                rs += __shfl_xor_sync(0xffffffffu, rs, off, 16);

            l_i[i] = l_i[i] * f + rs;
            #pragma unroll
            for (int j = 0; j < 4; j++) o[i][j] *= f;

            // stage P transposed for the PV GEMM
            #pragma unroll
            for (int j = 0; j < 4; j++)
                Pt[(tx * 4 + j) * PPAD + r] = s[i][j];
        }
        __syncthreads();

        // O += P V : 3x LDS.128 + 32 FMA per k
        #pragma unroll 8
        for (int k = 0; k < 64; k++) {
            float p[8], vv[4];
            *(float4*)&p[0] = *(const float4*)&Pt[k * PPAD + ty * 8];
            *(float4*)&p[4] = *(const float4*)&Pt[k * PPAD + ty * 8 + 4];
            *(float4*)&vv[0] = *(const float4*)&Vs[k * VPAD + tx * 4];
            #pragma unroll
            for (int i = 0; i < 8; i++)
                #pragma unroll
                for (int j = 0; j < 4; j++)
                    o[i][j] += p[i] * vv[j];
        }
        __syncthreads();   // protect Kt/Vs/Pt before next tile load
    }

    // Epilogue: normalize and store to merged-head layout [b*s][h*64+d]
    #pragma unroll
    for (int i = 0; i < 8; i++) {
        float inv = 1.0f / l_i[i];
        int s_row = q0 + ty * 8 + i;
        float4 val;
        val.x = o[i][0] * inv;
        val.y = o[i][1] * inv;
        val.z = o[i][2] * inv;
        val.w = o[i][3] * inv;
        *(float4*)&g_attn[(size_t)(b * S_ + s_row) * DM + h * DK + tx * 4] = val;
    }
}

// ---------------------------------------------------------------------------
extern "C" void kernel_launch(void* const* d_in, const int* in_sizes, int n_in,
                              void* d_out, int out_size)
{
    (void)in_sizes; (void)n_in; (void)out_size;
    const float* query = (const float*)d_in[0];
    const float* key   = (const float*)d_in[1];
    const float* value = (const float*)d_in[2];
    const int*   mask  = (const int*)d_in[3];
    const float* Wq    = (const float*)d_in[4];
    const float* bq    = (const float*)d_in[5];
    const float* Wk    = (const float*)d_in[6];
    const float* bk    = (const float*)d_in[7];
    const float* Wv    = (const float*)d_in[8];
    const float* bv    = (const float*)d_in[9];
    const float* Wo    = (const float*)d_in[10];
    const float* bo    = (const float*)d_in[11];
    float* out = (float*)d_out;

    // 1) QKV projections (fused into one launch via gridDim.z)
    dim3 gproj(M_ / BM, DM / BN, 3);   // (32, 8, 3)
    qkv_proj_kernel<<<gproj, 256>>>(query, key, value, Wq, Wk, Wv, bq, bk, bv);

    // 2) Flash attention
    cudaFuncSetAttribute(flash_kernel,
                         cudaFuncAttributeMaxDynamicSharedMemorySize, FLASH_SMEM);
    dim3 gflash(S_ / FBM, H_, B_);     // (16, 16, 2)
    flash_kernel<<<gflash, 256, FLASH_SMEM>>>(mask);

    // 3) Output projection
    dim3 gout(M_ / BM, DM / BN);       // (32, 8)
    out_proj_kernel<<<gout, 256>>>(Wo, bo, out);
}

// round 10
// speedup vs baseline: 1.5823x; 1.3678x over previous
#include <cuda_runtime.h>
#include <cuda_bf16.h>
#include <cstdint>

// ---------------------------------------------------------------------------
// MultiHeadedAttention: B=2, S=2048, H=16, d_k=64, d_model=1024, fp32.
// R6: projection GEMMs on mma.sync bf16 (hi/lo 3-pass, fp32 accum) --
// tcgen05 is rejected by the harness's compute_103 PTX target, but HMMA
// (sm_80-era mma.sync) is legal. Flash attention stays fp32 SIMT (R2).
// ---------------------------------------------------------------------------

#define B_  2
#define S_  2048
#define H_  16
#define DK  64
#define DM  1024
#define M_  (B_ * S_)   // 4096

__device__ float g_Q[(size_t)B_ * H_ * S_ * DK];     // [b][h][s][d]
__device__ float g_K[(size_t)B_ * H_ * S_ * DK];
__device__ float g_V[(size_t)B_ * H_ * S_ * DK];
__device__ float g_attn[(size_t)M_ * DM];            // [b*s][h*64+d]

// ===========================================================================
// mma.sync helpers (bf16, fp32 accum)
// ===========================================================================
__device__ __forceinline__ uint32_t smem_u32(const void* p) {
    uint32_t a;
    asm("{ .reg .u64 t; cvta.to.shared.u64 t, %1; cvt.u32.u64 %0, t; }"
        : "=r"(a) : "l"(p));
    return a;
}

__device__ __forceinline__ void ldsm_x4(uint32_t (&r)[4], uint32_t addr) {
    asm volatile("ldmatrix.sync.aligned.m8n8.x4.shared.b16 {%0,%1,%2,%3}, [%4];"
        : "=r"(r[0]), "=r"(r[1]), "=r"(r[2]), "=r"(r[3]) : "r"(addr));
}
__device__ __forceinline__ void ldsm_x2(uint32_t (&r)[2], uint32_t addr) {
    asm volatile("ldmatrix.sync.aligned.m8n8.x2.shared.b16 {%0,%1}, [%2];"
        : "=r"(r[0]), "=r"(r[1]) : "r"(addr));
}
__device__ __forceinline__ void mma_bf16(float (&d)[4], const uint32_t (&a)[4],
                                         const uint32_t (&b)[2]) {
    asm volatile(
        "mma.sync.aligned.m16n8k16.row.col.f32.bf16.bf16.f32 "
        "{%0,%1,%2,%3}, {%4,%5,%6,%7}, {%8,%9}, {%0,%1,%2,%3};"
        : "+f"(d[0]), "+f"(d[1]), "+f"(d[2]), "+f"(d[3])
        : "r"(a[0]), "r"(a[1]), "r"(a[2]), "r"(a[3]), "r"(b[0]), "r"(b[1]));
}

// ===========================================================================
// Projection GEMM: Y[128,128] tile of X[M,1024] @ W[1024,1024]^T.
// K chunk = 64 fp32 -> bf16 tiles 128 rows x 64 cols, row stride 144 B
// (9 x 16B chunks: ldmatrix bank rotation 4r mod 32 -> conflict-free).
// 3 passes: Ahi*Bhi + Ahi*Blo + Alo*Bhi, fp32 accumulators in registers.
// ===========================================================================
#define KC        64
#define NCHUNK    (DM / KC)          // 16
#define ROWB      144                // bytes per smem row (72 bf16)
#define TILE_B    (128 * ROWB)       // 18432 B
#define OFF_AHI   0
#define OFF_ALO   TILE_B
#define OFF_BHI   (2 * TILE_B)
#define OFF_BLO   (3 * TILE_B)
#define GEMM_SMEM (4 * TILE_B)       // 73728 B

// load 128x64 fp32 tile, convert to hi/lo bf16, store padded rows
__device__ __forceinline__ void load_conv_tile(
    const float* __restrict__ src, int row0, int k0,
    char* smem, uint32_t hi_off, uint32_t lo_off, int tid)
{
    #pragma unroll
    for (int v = tid; v < 2048; v += 256) {          // 8 iters
        int row = v >> 4;
        int c4  = (v & 15) * 4;
        float4 x = *(const float4*)(src + (size_t)(row0 + row) * DM + k0 + c4);

        __nv_bfloat16 h0 = __float2bfloat16(x.x);
        __nv_bfloat16 h1 = __float2bfloat16(x.y);
        __nv_bfloat16 h2 = __float2bfloat16(x.z);
        __nv_bfloat16 h3 = __float2bfloat16(x.w);
        __nv_bfloat16 l0 = __float2bfloat16(x.x - __bfloat162float(h0));
        __nv_bfloat16 l1 = __float2bfloat16(x.y - __bfloat162float(h1));
        __nv_bfloat16 l2 = __float2bfloat16(x.z - __bfloat162float(h2));
        __nv_bfloat16 l3 = __float2bfloat16(x.w - __bfloat162float(h3));

        uint2 H, L;
        H.x = (uint32_t)__bfloat16_as_ushort(h0) | ((uint32_t)__bfloat16_as_ushort(h1) << 16);
        H.y = (uint32_t)__bfloat16_as_ushort(h2) | ((uint32_t)__bfloat16_as_ushort(h3) << 16);
        L.x = (uint32_t)__bfloat16_as_ushort(l0) | ((uint32_t)__bfloat16_as_ushort(l1) << 16);
        L.y = (uint32_t)__bfloat16_as_ushort(l2) | ((uint32_t)__bfloat16_as_ushort(l3) << 16);

        uint32_t off = (uint32_t)row * ROWB + (uint32_t)c4 * 2;
        *(uint2*)(smem + hi_off + off) = H;
        *(uint2*)(smem + lo_off + off) = L;
    }
}

// one K-chunk of MMAs; d[mi][ni][4] accumulators for a 64x32 warp tile
__device__ __forceinline__ void mma_chunk(
    uint32_t smem_base, int warp_m, int warp_n, int lane, float d[4][4][4])
{
    const uint32_t aRow = (uint32_t)(warp_m * 64 + (lane & 15)) * ROWB
                        + ((lane >> 4) & 1) * 16;
    const uint32_t bRow = (uint32_t)(warp_n * 32 + (lane & 7)) * ROWB
                        + ((lane >> 3) & 1) * 16;

    #pragma unroll
    for (int ks = 0; ks < 4; ks++) {
        const uint32_t kb = (uint32_t)ks * 32;
        uint32_t bh[4][2], bl[4][2];
        #pragma unroll
        for (int ni = 0; ni < 4; ni++) {
            uint32_t baddr = smem_base + OFF_BHI + bRow + (uint32_t)ni * 8 * ROWB + kb;
            ldsm_x2(bh[ni], baddr);
            ldsm_x2(bl[ni], baddr + (OFF_BLO - OFF_BHI));
        }
        #pragma unroll
        for (int mi = 0; mi < 4; mi++) {
            uint32_t aaddr = smem_base + OFF_AHI + aRow + (uint32_t)mi * 16 * ROWB + kb;
            uint32_t ah[4], al[4];
            ldsm_x4(ah, aaddr);
            ldsm_x4(al, aaddr + (OFF_ALO - OFF_AHI));
            #pragma unroll
            for (int ni = 0; ni < 4; ni++) {
                mma_bf16(d[mi][ni], ah, bh[ni]);
                mma_bf16(d[mi][ni], ah, bl[ni]);
                mma_bf16(d[mi][ni], al, bh[ni]);
            }
        }
    }
}

__device__ __forceinline__ void gemm_mainloop(
    const float* __restrict__ X, const float* __restrict__ W,
    int m0, int n0, char* smem, uint32_t smem_base,
    int warp_m, int warp_n, int lane, int tid, float d[4][4][4])
{
    for (int c = 0; c < NCHUNK; c++) {
        load_conv_tile(X, m0, c * KC, smem, OFF_AHI, OFF_ALO, tid);
        load_conv_tile(W, n0, c * KC, smem, OFF_BHI, OFF_BLO, tid);
        __syncthreads();
        mma_chunk(smem_base, warp_m, warp_n, lane, d);
        __syncthreads();
    }
}

// --------------------------- qkv projection --------------------------------
__global__ __launch_bounds__(256, 2) void qkv_mma_kernel(
    const float* __restrict__ q_in, const float* __restrict__ k_in,
    const float* __restrict__ v_in,
    const float* __restrict__ Wq, const float* __restrict__ Wk,
    const float* __restrict__ Wv,
    const float* __restrict__ bq, const float* __restrict__ bk,
    const float* __restrict__ bv)
{
    extern __shared__ char smem[];
    const uint32_t smem_base = smem_u32(smem);
    const int tid = threadIdx.x;
    const int lane = tid & 31, w = tid >> 5;
    const int warp_m = w & 1, warp_n = w >> 1;

    const float *X, *W, *bias;
    float* outg;
    if (blockIdx.z == 0)      { X = q_in; W = Wq; bias = bq; outg = g_Q; }
    else if (blockIdx.z == 1) { X = k_in; W = Wk; bias = bk; outg = g_K; }
    else                      { X = v_in; W = Wv; bias = bv; outg = g_V; }

    float d[4][4][4];
    #pragma unroll
    for (int i = 0; i < 4; i++)
        #pragma unroll
        for (int j = 0; j < 4; j++)
            #pragma unroll
            for (int k = 0; k < 4; k++) d[i][j][k] = 0.f;

    const int m0 = blockIdx.x * 128;
    const int n0 = blockIdx.y * 128;
    gemm_mainloop(X, W, m0, n0, smem, smem_base, warp_m, warp_n, lane, tid, d);

    // epilogue: head-split layout [b][h][s][dk], float2 stores
    #pragma unroll
    for (int mi = 0; mi < 4; mi++) {
        int r = m0 + warp_m * 64 + mi * 16 + (lane >> 2);
        int bb = r >> 11;
        int s  = r & (S_ - 1);
        #pragma unroll
        for (int ni = 0; ni < 4; ni++) {
            int c  = n0 + warp_n * 32 + ni * 8 + (lane & 3) * 2;
            int h  = c >> 6;
            int dd = c & 63;
            float2 v0 = { d[mi][ni][0] + bias[c], d[mi][ni][1] + bias[c + 1] };
            float2 v1 = { d[mi][ni][2] + bias[c], d[mi][ni][3] + bias[c + 1] };
            float* base = outg + ((size_t)(bb * H_ + h) * S_) * DK;
            *(float2*)&base[(size_t)s * DK + dd]       = v0;
            *(float2*)&base[(size_t)(s + 8) * DK + dd] = v1;
        }
    }
}

// --------------------------- output projection -----------------------------
__global__ __launch_bounds__(256, 2) void out_mma_kernel(
    const float* __restrict__ Wo, const float* __restrict__ bo,
    float* __restrict__ out)
{
    extern __shared__ char smem[];
    const uint32_t smem_base = smem_u32(smem);
    const int tid = threadIdx.x;
    const int lane = tid & 31, w = tid >> 5;
    const int warp_m = w & 1, warp_n = w >> 1;

    float d[4][4][4];
    #pragma unroll
    for (int i = 0; i < 4; i++)
        #pragma unroll
        for (int j = 0; j < 4; j++)
            #pragma unroll
            for (int k = 0; k < 4; k++) d[i][j][k] = 0.f;

    const int m0 = blockIdx.x * 128;
    const int n0 = blockIdx.y * 128;
    gemm_mainloop(g_attn, Wo, m0, n0, smem, smem_base, warp_m, warp_n, lane, tid, d);

    #pragma unroll
    for (int mi = 0; mi < 4; mi++) {
        int r = m0 + warp_m * 64 + mi * 16 + (lane >> 2);
        #pragma unroll
        for (int ni = 0; ni < 4; ni++) {
            int c = n0 + warp_n * 32 + ni * 8 + (lane & 3) * 2;
            float2 v0 = { d[mi][ni][0] + bo[c], d[mi][ni][1] + bo[c + 1] };
            float2 v1 = { d[mi][ni][2] + bo[c], d[mi][ni][3] + bo[c + 1] };
            *(float2*)&out[(size_t)r * DM + c]       = v0;
            *(float2*)&out[(size_t)(r + 8) * DM + c] = v1;
        }
    }
}

// ===========================================================================
// Flash attention (R2 SIMT version, unchanged)
// ===========================================================================
#define FBM 128
#define FBN 64
#define QPAD 132
#define KPAD 68
#define VPAD 68
#define PPAD 140
#define SM_QT (64 * QPAD)
#define SM_KT (64 * KPAD)
#define SM_VS (64 * VPAD)
#define SM_PT (64 * PPAD)
#define FLASH_SMEM ((SM_QT + SM_KT + SM_VS + SM_PT) * (int)sizeof(float))

__global__ __launch_bounds__(256, 2) void flash_kernel(const int* __restrict__ mask)
{
    extern __shared__ float fsmem[];
    float* Qt = fsmem;
    float* Kt = Qt + SM_QT;
    float* Vs = Kt + SM_KT;
    float* Pt = Vs + SM_VS;

    const int tid = threadIdx.x;
    const int tx  = tid & 15;
    const int ty  = tid >> 4;
    const int q0  = blockIdx.x * FBM;
    const int h   = blockIdx.y;
    const int b   = blockIdx.z;

    const float* Qg = g_Q + (size_t)(b * H_ + h) * S_ * DK;
    const float* Kg = g_K + (size_t)(b * H_ + h) * S_ * DK;
    const float* Vg = g_V + (size_t)(b * H_ + h) * S_ * DK;
    const int*   Mg = mask + (size_t)b * S_ * S_;

    const float qscale = 0.125f;
    #pragma unroll
    for (int v = tid; v < 128 * 16; v += 256) {
        int r  = v & 127;
        int d4 = (v >> 7) * 4;
        float4 q = *(const float4*)(Qg + (size_t)(q0 + r) * DK + d4);
        Qt[(d4 + 0) * QPAD + r] = q.x * qscale;
        Qt[(d4 + 1) * QPAD + r] = q.y * qscale;
        Qt[(d4 + 2) * QPAD + r] = q.z * qscale;
        Qt[(d4 + 3) * QPAD + r] = q.w * qscale;
    }

    float m_i[8], l_i[8], o[8][4];
    #pragma unroll
    for (int i = 0; i < 8; i++) {
        m_i[i] = -1e30f;
        l_i[i] = 0.f;
        #pragma unroll
        for (int j = 0; j < 4; j++) o[i][j] = 0.f;
    }

    for (int n0t = 0; n0t < S_; n0t += FBN) {
        #pragma unroll
        for (int v = tid; v < 64 * 16; v += 256) {
            int c  = v & 63;
            int d4 = (v >> 6) * 4;
            float4 kk = *(const float4*)(Kg + (size_t)(n0t + c) * DK + d4);
            Kt[(d4 + 0) * KPAD + c] = kk.x;
            Kt[(d4 + 1) * KPAD + c] = kk.y;
            Kt[(d4 + 2) * KPAD + c] = kk.z;
            Kt[(d4 + 3) * KPAD + c] = kk.w;
        }
        #pragma unroll
        for (int v = tid; v < 64 * 16; v += 256) {
            int k  = v >> 4;
            int c4 = (v & 15) * 4;
            float4 vv = *(const float4*)(Vg + (size_t)(n0t + k) * DK + c4);
            float* vd = &Vs[k * VPAD + c4];
            vd[0] = vv.x; vd[1] = vv.y; vd[2] = vv.z; vd[3] = vv.w;
        }
        __syncthreads();

        float s[8][4];
        #pragma unroll
        for (int i = 0; i < 8; i++)
            #pragma unroll
            for (int j = 0; j < 4; j++) s[i][j] = 0.f;

        #pragma unroll 8
        for (int d = 0; d < 64; d++) {
            float a[8], bb[4];
            *(float4*)&a[0] = *(const float4*)&Qt[d * QPAD + ty * 8];
            *(float4*)&a[4] = *(const float4*)&Qt[d * QPAD + ty * 8 + 4];
            *(float4*)&bb[0] = *(const float4*)&Kt[d * KPAD + tx * 4];
            #pragma unroll
            for (int i = 0; i < 8; i++)
                #pragma unroll
                for (int j = 0; j < 4; j++)
                    s[i][j] += a[i] * bb[j];
        }

        #pragma unroll
        for (int i = 0; i < 8; i++) {
            const int r = ty * 8 + i;
            int4 mm = *(const int4*)(Mg + (size_t)(q0 + r) * S_ + n0t + tx * 4);
            if (mm.x == 0) s[i][0] = -1e9f;
            if (mm.y == 0) s[i][1] = -1e9f;
            if (mm.z == 0) s[i][2] = -1e9f;
            if (mm.w == 0) s[i][3] = -1e9f;

            float mloc = fmaxf(fmaxf(s[i][0], s[i][1]), fmaxf(s[i][2], s[i][3]));
            #pragma unroll
            for (int off = 8; off >= 1; off >>= 1)
                mloc = fmaxf(mloc, __shfl_xor_sync(0xffffffffu, mloc, off, 16));

            float mn = fmaxf(m_i[i], mloc);
            float f  = __expf(m_i[i] - mn);
            m_i[i] = mn;

            float rs = 0.f;
            #pragma unroll
            for (int j = 0; j < 4; j++) {
                s[i][j] = __expf(s[i][j] - mn);
                rs += s[i][j];
            }
            #pragma unroll
            for (int off = 8; off >= 1; off >>= 1)
                rs += __shfl_xor_sync(0xffffffffu, rs, off, 16);

            l_i[i] = l_i[i] * f + rs;
            #pragma unroll
            for (int j = 0; j < 4; j++) o[i][j] *= f;

            #pragma unroll
            for (int j = 0; j < 4; j++)
                Pt[(tx * 4 + j) * PPAD + r] = s[i][j];
        }
        __syncthreads();

        #pragma unroll 8
        for (int k = 0; k < 64; k++) {
            float p[8], vv[4];
            *(float4*)&p[0] = *(const float4*)&Pt[k * PPAD + ty * 8];
            *(float4*)&p[4] = *(const float4*)&Pt[k * PPAD + ty * 8 + 4];
            *(float4*)&vv[0] = *(const float4*)&Vs[k * VPAD + tx * 4];
            #pragma unroll
            for (int i = 0; i < 8; i++)
                #pragma unroll
                for (int j = 0; j < 4; j++)
                    o[i][j] += p[i] * vv[j];
        }
        __syncthreads();
    }

    #pragma unroll
    for (int i = 0; i < 8; i++) {
        float inv = 1.0f / l_i[i];
        int s_row = q0 + ty * 8 + i;
        float4 val;
        val.x = o[i][0] * inv;
        val.y = o[i][1] * inv;
        val.z = o[i][2] * inv;
        val.w = o[i][3] * inv;
        *(float4*)&g_attn[(size_t)(b * S_ + s_row) * DM + h * DK + tx * 4] = val;
    }
}

// ===========================================================================
extern "C" void kernel_launch(void* const* d_in, const int* in_sizes, int n_in,
                              void* d_out, int out_size)
{
    (void)in_sizes; (void)n_in; (void)out_size;
    const float* query = (const float*)d_in[0];
    const float* key   = (const float*)d_in[1];
    const float* value = (const float*)d_in[2];
    const int*   mask  = (const int*)d_in[3];
    const float* Wq    = (const float*)d_in[4];
    const float* bq    = (const float*)d_in[5];
    const float* Wk    = (const float*)d_in[6];
    const float* bk    = (const float*)d_in[7];
    const float* Wv    = (const float*)d_in[8];
    const float* bv    = (const float*)d_in[9];
    const float* Wo    = (const float*)d_in[10];
    const float* bo    = (const float*)d_in[11];
    float* out = (float*)d_out;

    cudaFuncSetAttribute(qkv_mma_kernel,
                         cudaFuncAttributeMaxDynamicSharedMemorySize, GEMM_SMEM);
    cudaFuncSetAttribute(out_mma_kernel,
                         cudaFuncAttributeMaxDynamicSharedMemorySize, GEMM_SMEM);
    cudaFuncSetAttribute(flash_kernel,
                         cudaFuncAttributeMaxDynamicSharedMemorySize, FLASH_SMEM);

    // 1) QKV projections (mma.sync bf16 hi/lo)
    dim3 gproj(M_ / 128, DM / 128, 3);   // (32, 8, 3)
    qkv_mma_kernel<<<gproj, 256, GEMM_SMEM>>>(query, key, value,
                                              Wq, Wk, Wv, bq, bk, bv);

    // 2) Flash attention (fp32 SIMT)
    dim3 gflash(S_ / FBM, H_, B_);       // (16, 16, 2)
    flash_kernel<<<gflash, 256, FLASH_SMEM>>>(mask);

    // 3) Output projection (mma.sync bf16 hi/lo)
    dim3 gout(M_ / 128, DM / 128);       // (32, 8)
    out_mma_kernel<<<gout, 256, GEMM_SMEM>>>(Wo, bo, out);
}

// round 13
// speedup vs baseline: 2.8034x; 1.7717x over previous
#include <cuda_runtime.h>
#include <cuda_bf16.h>
#include <cstdint>

// ---------------------------------------------------------------------------
// MultiHeadedAttention: B=2, S=2048, H=16, d_k=64, d_model=1024, fp32.
// R11: identical to R10 (bench failed on container init, not the kernel).
// EVERYTHING on mma.sync bf16 hi/lo 3-pass (projections AND flash
// attention). Q/K/V stored as bf16 hi/lo pairs by the projection kernel
// (Q pre-scaled by 1/8). Flash: 128-row q tiles, 64-col kv tiles, 8 warps
// x 16 rows, warp-private softmax + P staging, V via ldmatrix.trans.
// ---------------------------------------------------------------------------

#define B_  2
#define S_  2048
#define H_  16
#define DK  64
#define DM  1024
#define M_  (B_ * S_)   // 4096

#define QKV_ELEMS ((size_t)B_ * H_ * S_ * DK)
__device__ __align__(16) __nv_bfloat16 g_Qhi[QKV_ELEMS];  // pre-scaled by 1/8
__device__ __align__(16) __nv_bfloat16 g_Qlo[QKV_ELEMS];
__device__ __align__(16) __nv_bfloat16 g_Khi[QKV_ELEMS];
__device__ __align__(16) __nv_bfloat16 g_Klo[QKV_ELEMS];
__device__ __align__(16) __nv_bfloat16 g_Vhi[QKV_ELEMS];
__device__ __align__(16) __nv_bfloat16 g_Vlo[QKV_ELEMS];
__device__ __align__(16) float g_attn[(size_t)M_ * DM];   // [b*s][h*64+d]

// ===========================================================================
// mma.sync helpers (bf16, fp32 accum)
// ===========================================================================
__device__ __forceinline__ uint32_t smem_u32(const void* p) {
    uint32_t a;
    asm("{ .reg .u64 t; cvta.to.shared.u64 t, %1; cvt.u32.u64 %0, t; }"
        : "=r"(a) : "l"(p));
    return a;
}
__device__ __forceinline__ void ldsm_x4(uint32_t (&r)[4], uint32_t addr) {
    asm volatile("ldmatrix.sync.aligned.m8n8.x4.shared.b16 {%0,%1,%2,%3}, [%4];"
        : "=r"(r[0]), "=r"(r[1]), "=r"(r[2]), "=r"(r[3]) : "r"(addr));
}
__device__ __forceinline__ void ldsm_x4_t(uint32_t (&r)[4], uint32_t addr) {
    asm volatile("ldmatrix.sync.aligned.m8n8.x4.trans.shared.b16 {%0,%1,%2,%3}, [%4];"
        : "=r"(r[0]), "=r"(r[1]), "=r"(r[2]), "=r"(r[3]) : "r"(addr));
}
__device__ __forceinline__ void mma_bf16(float (&d)[4], const uint32_t (&a)[4],
                                         uint32_t b0, uint32_t b1) {
    asm volatile(
        "mma.sync.aligned.m16n8k16.row.col.f32.bf16.bf16.f32 "
        "{%0,%1,%2,%3}, {%4,%5,%6,%7}, {%8,%9}, {%0,%1,%2,%3};"
        : "+f"(d[0]), "+f"(d[1]), "+f"(d[2]), "+f"(d[3])
        : "r"(a[0]), "r"(a[1]), "r"(a[2]), "r"(a[3]), "r"(b0), "r"(b1));
}

// split x0,x1 into hi/lo bf16 pairs, packed as two uint32
__device__ __forceinline__ uint32_t pack_hl(float x0, float x1, uint32_t& lo) {
    __nv_bfloat16 h0 = __float2bfloat16(x0), h1 = __float2bfloat16(x1);
    __nv_bfloat16 l0 = __float2bfloat16(x0 - __bfloat162float(h0));
    __nv_bfloat16 l1 = __float2bfloat16(x1 - __bfloat162float(h1));
    lo = (uint32_t)__bfloat16_as_ushort(l0) | ((uint32_t)__bfloat16_as_ushort(l1) << 16);
    return (uint32_t)__bfloat16_as_ushort(h0) | ((uint32_t)__bfloat16_as_ushort(h1) << 16);
}

// ===========================================================================
// Projection GEMM machinery (R6, unchanged core)
// ===========================================================================
#define KC        64
#define NCHUNK    (DM / KC)
#define ROWB      144
#define TILE_B    (128 * ROWB)
#define OFF_AHI   0
#define OFF_ALO   TILE_B
#define OFF_BHI   (2 * TILE_B)
#define OFF_BLO   (3 * TILE_B)
#define GEMM_SMEM (4 * TILE_B)       // 73728 B

__device__ __forceinline__ void load_conv_tile(
    const float* __restrict__ src, int row0, int k0,
    char* smem, uint32_t hi_off, uint32_t lo_off, int tid)
{
    #pragma unroll
    for (int v = tid; v < 2048; v += 256) {
        int row = v >> 4;
        int c4  = (v & 15) * 4;
        float4 x = *(const float4*)(src + (size_t)(row0 + row) * DM + k0 + c4);
        uint32_t l0, l1, h0, h1;
        h0 = pack_hl(x.x, x.y, l0);
        h1 = pack_hl(x.z, x.w, l1);
        uint32_t off = (uint32_t)row * ROWB + (uint32_t)c4 * 2;
        *(uint2*)(smem + hi_off + off) = make_uint2(h0, h1);
        *(uint2*)(smem + lo_off + off) = make_uint2(l0, l1);
    }
}

__device__ __forceinline__ void mma_chunk(
    uint32_t smem_base, int warp_m, int warp_n, int lane, float d[4][4][4])
{
    const uint32_t aRow = (uint32_t)(warp_m * 64 + (lane & 15)) * ROWB
                        + ((lane >> 4) & 1) * 16;
    const uint32_t bRow = (uint32_t)(warp_n * 32 + (lane & 7)) * ROWB
                        + ((lane >> 3) & 1) * 16;
    #pragma unroll
    for (int ks = 0; ks < 4; ks++) {
        const uint32_t kb = (uint32_t)ks * 32;
        uint32_t bh[4][2], bl[4][2];
        #pragma unroll
        for (int ni = 0; ni < 4; ni++) {
            uint32_t baddr = smem_base + OFF_BHI + bRow + (uint32_t)ni * 8 * ROWB + kb;
            asm volatile("ldmatrix.sync.aligned.m8n8.x2.shared.b16 {%0,%1}, [%2];"
                : "=r"(bh[ni][0]), "=r"(bh[ni][1]) : "r"(baddr));
            asm volatile("ldmatrix.sync.aligned.m8n8.x2.shared.b16 {%0,%1}, [%2];"
                : "=r"(bl[ni][0]), "=r"(bl[ni][1]) : "r"(baddr + (OFF_BLO - OFF_BHI)));
        }
        #pragma unroll
        for (int mi = 0; mi < 4; mi++) {
            uint32_t aaddr = smem_base + OFF_AHI + aRow + (uint32_t)mi * 16 * ROWB + kb;
            uint32_t ah[4], al[4];
            ldsm_x4(ah, aaddr);
            ldsm_x4(al, aaddr + (OFF_ALO - OFF_AHI));
            #pragma unroll
            for (int ni = 0; ni < 4; ni++) {
                mma_bf16(d[mi][ni], ah, bh[ni][0], bh[ni][1]);
                mma_bf16(d[mi][ni], ah, bl[ni][0], bl[ni][1]);
                mma_bf16(d[mi][ni], al, bh[ni][0], bh[ni][1]);
            }
        }
    }
}

__device__ __forceinline__ void gemm_mainloop(
    const float* __restrict__ X, const float* __restrict__ W,
    int m0, int n0, char* smem, uint32_t smem_base,
    int warp_m, int warp_n, int lane, int tid, float d[4][4][4])
{
    for (int c = 0; c < NCHUNK; c++) {
        load_conv_tile(X, m0, c * KC, smem, OFF_AHI, OFF_ALO, tid);
        load_conv_tile(W, n0, c * KC, smem, OFF_BHI, OFF_BLO, tid);
        __syncthreads();
        mma_chunk(smem_base, warp_m, warp_n, lane, d);
        __syncthreads();
    }
}

// --------------------------- qkv projection --------------------------------
// Epilogue writes bf16 hi/lo head-split tensors; Q pre-scaled by 1/8.
__global__ __launch_bounds__(256, 2) void qkv_mma_kernel(
    const float* __restrict__ q_in, const float* __restrict__ k_in,
    const float* __restrict__ v_in,
    const float* __restrict__ Wq, const float* __restrict__ Wk,
    const float* __restrict__ Wv,
    const float* __restrict__ bq, const float* __restrict__ bk,
    const float* __restrict__ bv)
{
    extern __shared__ char smem[];
    const uint32_t smem_base = smem_u32(smem);
    const int tid = threadIdx.x;
    const int lane = tid & 31, w = tid >> 5;
    const int warp_m = w & 1, warp_n = w >> 1;

    const float *X, *W, *bias;
    __nv_bfloat16 *ghi, *glo;
    float scale;
    if (blockIdx.z == 0)      { X = q_in; W = Wq; bias = bq; ghi = g_Qhi; glo = g_Qlo; scale = 0.125f; }
    else if (blockIdx.z == 1) { X = k_in; W = Wk; bias = bk; ghi = g_Khi; glo = g_Klo; scale = 1.0f; }
    else                      { X = v_in; W = Wv; bias = bv; ghi = g_Vhi; glo = g_Vlo; scale = 1.0f; }

    float d[4][4][4];
    #pragma unroll
    for (int i = 0; i < 4; i++)
        #pragma unroll
        for (int j = 0; j < 4; j++)
            #pragma unroll
            for (int k = 0; k < 4; k++) d[i][j][k] = 0.f;

    const int m0 = blockIdx.x * 128;
    const int n0 = blockIdx.y * 128;
    gemm_mainloop(X, W, m0, n0, smem, smem_base, warp_m, warp_n, lane, tid, d);

    #pragma unroll
    for (int mi = 0; mi < 4; mi++) {
        int r  = m0 + warp_m * 64 + mi * 16 + (lane >> 2);
        int bb = r >> 11;
        int s  = r & (S_ - 1);
        #pragma unroll
        for (int ni = 0; ni < 4; ni++) {
            int c  = n0 + warp_n * 32 + ni * 8 + (lane & 3) * 2;
            int h  = c >> 6;
            int dd = c & 63;
            size_t idx0 = ((size_t)(bb * H_ + h) * S_ + s) * DK + dd;
            size_t idx1 = idx0 + 8 * DK;   // row +8 (same head/batch)
            float x0 = (d[mi][ni][0] + bias[c])     * scale;
            float x1 = (d[mi][ni][1] + bias[c + 1]) * scale;
            float x2 = (d[mi][ni][2] + bias[c])     * scale;
            float x3 = (d[mi][ni][3] + bias[c + 1]) * scale;
            uint32_t lo0, lo1, hi0, hi1;
            hi0 = pack_hl(x0, x1, lo0);
            hi1 = pack_hl(x2, x3, lo1);
            *(uint32_t*)&ghi[idx0] = hi0;
            *(uint32_t*)&glo[idx0] = lo0;
            *(uint32_t*)&ghi[idx1] = hi1;
            *(uint32_t*)&glo[idx1] = lo1;
        }
    }
}

// --------------------------- output projection -----------------------------
__global__ __launch_bounds__(256, 2) void out_mma_kernel(
    const float* __restrict__ Wo, const float* __restrict__ bo,
    float* __restrict__ out)
{
    extern __shared__ char smem[];
    const uint32_t smem_base = smem_u32(smem);
    const int tid = threadIdx.x;
    const int lane = tid & 31, w = tid >> 5;
    const int warp_m = w & 1, warp_n = w >> 1;

    float d[4][4][4];
    #pragma unroll
    for (int i = 0; i < 4; i++)
        #pragma unroll
        for (int j = 0; j < 4; j++)
            #pragma unroll
            for (int k = 0; k < 4; k++) d[i][j][k] = 0.f;

    const int m0 = blockIdx.x * 128;
    const int n0 = blockIdx.y * 128;
    gemm_mainloop(g_attn, Wo, m0, n0, smem, smem_base, warp_m, warp_n, lane, tid, d);

    #pragma unroll
    for (int mi = 0; mi < 4; mi++) {
        int r = m0 + warp_m * 64 + mi * 16 + (lane >> 2);
        #pragma unroll
        for (int ni = 0; ni < 4; ni++) {
            int c = n0 + warp_n * 32 + ni * 8 + (lane & 3) * 2;
            float2 v0 = { d[mi][ni][0] + bo[c], d[mi][ni][1] + bo[c + 1] };
            float2 v1 = { d[mi][ni][2] + bo[c], d[mi][ni][3] + bo[c + 1] };
            *(float2*)&out[(size_t)r * DM + c]       = v0;
            *(float2*)&out[(size_t)(r + 8) * DM + c] = v1;
        }
    }
}

// ===========================================================================
// Flash attention on mma.sync: 128 q-rows/CTA, 64-col kv tiles, 8 warps x
// 16 rows. All smem rows stride 144 B. 3-pass hi/lo for QK and PV.
// ===========================================================================
#define FROWB    144
#define F_KHI    0                       // K: 64 rows
#define F_KLO    (F_KHI + 64 * FROWB)
#define F_VHI    (F_KLO + 64 * FROWB)    // V: 64 rows (natural [kv][d])
#define F_VLO    (F_VHI + 64 * FROWB)
#define F_QHI    (F_VLO + 64 * FROWB)    // Q: 128 rows
#define F_QLO    (F_QHI + 128 * FROWB)
#define F_PHI    (F_QLO + 128 * FROWB)   // P: 128 rows
#define F_PLO    (F_PHI + 128 * FROWB)
#define FLASH_SMEM (F_PLO + 128 * FROWB) // 110,592 B

__global__ __launch_bounds__(256, 2) void flash_mma_kernel(const int* __restrict__ mask)
{
    extern __shared__ char fsm[];
    const uint32_t base = smem_u32(fsm);
    const int tid  = threadIdx.x;
    const int lane = tid & 31;
    const int w    = tid >> 5;           // warp 0..7: rows w*16..w*16+15
    const int q0   = blockIdx.x * 128;
    const int h    = blockIdx.y;
    const int b    = blockIdx.z;

    const __nv_bfloat16* Qh = g_Qhi + (size_t)(b * H_ + h) * S_ * DK;
    const __nv_bfloat16* Ql = g_Qlo + (size_t)(b * H_ + h) * S_ * DK;
    const __nv_bfloat16* Kh = g_Khi + (size_t)(b * H_ + h) * S_ * DK;
    const __nv_bfloat16* Kl = g_Klo + (size_t)(b * H_ + h) * S_ * DK;
    const __nv_bfloat16* Vh = g_Vhi + (size_t)(b * H_ + h) * S_ * DK;
    const __nv_bfloat16* Vl = g_Vlo + (size_t)(b * H_ + h) * S_ * DK;
    const int* Mg = mask + (size_t)b * S_ * S_;

    // Load Q tile (128 rows x 64 bf16 = 8 x 16B chunks per row)
    #pragma unroll
    for (int v = tid; v < 1024; v += 256) {
        int row = v >> 3, ch = v & 7;
        uint32_t off = (uint32_t)row * FROWB + (uint32_t)ch * 16;
        *(uint4*)(fsm + F_QHI + off) = *(const uint4*)(Qh + (size_t)(q0 + row) * DK + ch * 8);
        *(uint4*)(fsm + F_QLO + off) = *(const uint4*)(Ql + (size_t)(q0 + row) * DK + ch * 8);
    }

    // fragment base addresses (lane-dependent)
    const uint32_t qbase = base + F_QHI + (uint32_t)(w * 16 + (lane & 15)) * FROWB
                         + ((lane >> 4) & 1) * 16;
    const uint32_t kbase = base + F_KHI + (uint32_t)(((lane >> 4) & 1) * 8 + (lane & 7)) * FROWB
                         + ((lane >> 3) & 1) * 16;
    const uint32_t pbase = base + F_PHI + (uint32_t)(w * 16 + (lane & 15)) * FROWB
                         + ((lane >> 4) & 1) * 16;
    const uint32_t vbase = base + F_VHI + (uint32_t)(((lane >> 3) & 1) * 8 + (lane & 7)) * FROWB
                         + ((lane >> 4) & 1) * 16;

    // per-thread softmax state: rows r_lo = w*16 + (lane>>2), r_hi = +8
    float m0r = -1e30f, m1r = -1e30f, l0r = 0.f, l1r = 0.f;
    float o[8][4];
    #pragma unroll
    for (int i = 0; i < 8; i++)
        #pragma unroll
        for (int j = 0; j < 4; j++) o[i][j] = 0.f;

    const int rg0 = q0 + w * 16 + (lane >> 2);   // global q row (lo)
    const int cg  = (lane & 3) * 2;              // col offset within n8 tile

    for (int n0t = 0; n0t < S_; n0t += 64) {
        // ---- load K, V tiles (64 rows x 8 chunks each, hi+lo) ----
        #pragma unroll
        for (int v = tid; v < 512; v += 256) {
            int row = v >> 3, ch = v & 7;
            uint32_t off = (uint32_t)row * FROWB + (uint32_t)ch * 16;
            const size_t g = (size_t)(n0t + row) * DK + ch * 8;
            *(uint4*)(fsm + F_KHI + off) = *(const uint4*)(Kh + g);
            *(uint4*)(fsm + F_KLO + off) = *(const uint4*)(Kl + g);
            *(uint4*)(fsm + F_VHI + off) = *(const uint4*)(Vh + g);
            *(uint4*)(fsm + F_VLO + off) = *(const uint4*)(Vl + g);
        }
        __syncthreads();

        // ---- S = (Q/8) K^T : 3-pass hi/lo ----
        float s[8][4];
        #pragma unroll
        for (int i = 0; i < 8; i++)
            #pragma unroll
            for (int j = 0; j < 4; j++) s[i][j] = 0.f;

        #pragma unroll
        for (int ks = 0; ks < 4; ks++) {
            uint32_t aH[4], aL[4];
            ldsm_x4(aH, qbase + ks * 32);
            ldsm_x4(aL, qbase + (F_QLO - F_QHI) + ks * 32);
            #pragma unroll
            for (int nip = 0; nip < 4; nip++) {
                uint32_t kh[4], kl[4];
                uint32_t ka = kbase + (uint32_t)nip * 16 * FROWB + ks * 32;
                ldsm_x4(kh, ka);
                ldsm_x4(kl, ka + (F_KLO - F_KHI));
                mma_bf16(s[2 * nip],     aH, kh[0], kh[1]);
                mma_bf16(s[2 * nip],     aH, kl[0], kl[1]);
                mma_bf16(s[2 * nip],     aL, kh[0], kh[1]);
                mma_bf16(s[2 * nip + 1], aH, kh[2], kh[3]);
                mma_bf16(s[2 * nip + 1], aH, kl[2], kl[3]);
                mma_bf16(s[2 * nip + 1], aL, kh[2], kh[3]);
            }
        }

        // ---- mask ----
        #pragma unroll
        for (int ni = 0; ni < 8; ni++) {
            int c = n0t + ni * 8 + cg;
            int2 mm0 = *(const int2*)(Mg + (size_t)rg0 * S_ + c);
            int2 mm1 = *(const int2*)(Mg + (size_t)(rg0 + 8) * S_ + c);
            if (mm0.x == 0) s[ni][0] = -1e9f;
            if (mm0.y == 0) s[ni][1] = -1e9f;
            if (mm1.x == 0) s[ni][2] = -1e9f;
            if (mm1.y == 0) s[ni][3] = -1e9f;
        }

        // ---- online softmax (row groups = 4 lanes sharing lane>>2) ----
        float mx0 = -1e30f, mx1 = -1e30f;
        #pragma unroll
        for (int ni = 0; ni < 8; ni++) {
            mx0 = fmaxf(mx0, fmaxf(s[ni][0], s[ni][1]));
            mx1 = fmaxf(mx1, fmaxf(s[ni][2], s[ni][3]));
        }
        mx0 = fmaxf(mx0, __shfl_xor_sync(0xffffffffu, mx0, 1));
        mx0 = fmaxf(mx0, __shfl_xor_sync(0xffffffffu, mx0, 2));
        mx1 = fmaxf(mx1, __shfl_xor_sync(0xffffffffu, mx1, 1));
        mx1 = fmaxf(mx1, __shfl_xor_sync(0xffffffffu, mx1, 2));

        float mn0 = fmaxf(m0r, mx0), mn1 = fmaxf(m1r, mx1);
        float f0 = __expf(m0r - mn0), f1 = __expf(m1r - mn1);
        m0r = mn0; m1r = mn1;

        float sum0 = 0.f, sum1 = 0.f;
        #pragma unroll
        for (int ni = 0; ni < 8; ni++) {
            s[ni][0] = __expf(s[ni][0] - mn0);
            s[ni][1] = __expf(s[ni][1] - mn0);
            s[ni][2] = __expf(s[ni][2] - mn1);
            s[ni][3] = __expf(s[ni][3] - mn1);
            sum0 += s[ni][0] + s[ni][1];
            sum1 += s[ni][2] + s[ni][3];
        }
        sum0 += __shfl_xor_sync(0xffffffffu, sum0, 1);
        sum0 += __shfl_xor_sync(0xffffffffu, sum0, 2);
        sum1 += __shfl_xor_sync(0xffffffffu, sum1, 1);
        sum1 += __shfl_xor_sync(0xffffffffu, sum1, 2);
        l0r = l0r * f0 + sum0;
        l1r = l1r * f1 + sum1;

        #pragma unroll
        for (int ni = 0; ni < 8; ni++) {
            o[ni][0] *= f0; o[ni][1] *= f0;
            o[ni][2] *= f1; o[ni][3] *= f1;
        }

        // ---- stage P as bf16 hi/lo (warp-private rows) ----
        #pragma unroll
        for (int ni = 0; ni < 8; ni++) {
            uint32_t cbyte = (uint32_t)(ni * 8 + cg) * 2;
            uint32_t r0off = (uint32_t)(w * 16 + (lane >> 2)) * FROWB + cbyte;
            uint32_t lo0, lo1, hi0, hi1;
            hi0 = pack_hl(s[ni][0], s[ni][1], lo0);
            hi1 = pack_hl(s[ni][2], s[ni][3], lo1);
            *(uint32_t*)(fsm + F_PHI + r0off)             = hi0;
            *(uint32_t*)(fsm + F_PLO + r0off)             = lo0;
            *(uint32_t*)(fsm + F_PHI + r0off + 8 * FROWB) = hi1;
            *(uint32_t*)(fsm + F_PLO + r0off + 8 * FROWB) = lo1;
        }
        __syncwarp();

        // ---- O += P V : 3-pass hi/lo, V via ldmatrix.trans ----
        #pragma unroll
        for (int ks = 0; ks < 4; ks++) {
            uint32_t pH[4], pL[4];
            ldsm_x4(pH, pbase + ks * 32);
            ldsm_x4(pL, pbase + (F_PLO - F_PHI) + ks * 32);
            #pragma unroll
            for (int nip = 0; nip < 4; nip++) {
                uint32_t vh[4], vl[4];
                uint32_t va = vbase + (uint32_t)ks * 16 * FROWB + (uint32_t)nip * 32;
                ldsm_x4_t(vh, va);
                ldsm_x4_t(vl, va + (F_VLO - F_VHI));
                mma_bf16(o[2 * nip],     pH, vh[0], vh[1]);
                mma_bf16(o[2 * nip],     pH, vl[0], vl[1]);
                mma_bf16(o[2 * nip],     pL, vh[0], vh[1]);
                mma_bf16(o[2 * nip + 1], pH, vh[2], vh[3]);
                mma_bf16(o[2 * nip + 1], pH, vl[2], vl[3]);
                mma_bf16(o[2 * nip + 1], pL, vh[2], vh[3]);
            }
        }
        __syncthreads();   // protect K/V (and P read-before-overwrite) for next tile
    }

    // ---- epilogue: normalize, store fp32 to merged-head layout ----
    float inv0 = 1.0f / l0r, inv1 = 1.0f / l1r;
    #pragma unroll
    for (int ni = 0; ni < 8; ni++) {
        int dd = h * DK + ni * 8 + cg;
        float2 v0 = { o[ni][0] * inv0, o[ni][1] * inv0 };
        float2 v1 = { o[ni][2] * inv1, o[ni][3] * inv1 };
        *(float2*)&g_attn[(size_t)(b * S_ + rg0) * DM + dd]       = v0;
        *(float2*)&g_attn[(size_t)(b * S_ + rg0 + 8) * DM + dd]   = v1;
    }
}

// ===========================================================================
extern "C" void kernel_launch(void* const* d_in, const int* in_sizes, int n_in,
                              void* d_out, int out_size)
{
    (void)in_sizes; (void)n_in; (void)out_size;
    const float* query = (const float*)d_in[0];
    const float* key   = (const float*)d_in[1];
    const float* value = (const float*)d_in[2];
    const int*   mask  = (const int*)d_in[3];
    const float* Wq    = (const float*)d_in[4];
    const float* bq    = (const float*)d_in[5];
    const float* Wk    = (const float*)d_in[6];
    const float* bk    = (const float*)d_in[7];
    const float* Wv    = (const float*)d_in[8];
    const float* bv    = (const float*)d_in[9];
    const float* Wo    = (const float*)d_in[10];
    const float* bo    = (const float*)d_in[11];
    float* out = (float*)d_out;

    cudaFuncSetAttribute(qkv_mma_kernel,
                         cudaFuncAttributeMaxDynamicSharedMemorySize, GEMM_SMEM);
    cudaFuncSetAttribute(out_mma_kernel,
                         cudaFuncAttributeMaxDynamicSharedMemorySize, GEMM_SMEM);
    cudaFuncSetAttribute(flash_mma_kernel,
                         cudaFuncAttributeMaxDynamicSharedMemorySize, FLASH_SMEM);

    // 1) QKV projections -> bf16 hi/lo head-split tensors (Q pre-scaled)
    dim3 gproj(M_ / 128, DM / 128, 3);   // (32, 8, 3)
    qkv_mma_kernel<<<gproj, 256, GEMM_SMEM>>>(query, key, value,
                                              Wq, Wk, Wv, bq, bk, bv);

    // 2) Flash attention on mma.sync
    dim3 gflash(S_ / 128, H_, B_);       // (16, 16, 2)
    flash_mma_kernel<<<gflash, 256, FLASH_SMEM>>>(mask);

    // 3) Output projection
    dim3 gout(M_ / 128, DM / 128);       // (32, 8)
    out_mma_kernel<<<gout, 256, GEMM_SMEM>>>(Wo, bo, out);
}